// round 8
// baseline (speedup 1.0000x reference)
#include <cuda_runtime.h>
#include <math.h>

#define N_NODES   50000
#define N_EDGES   800000
#define E_TOT     (N_EDGES + N_NODES)   // 850000 (with self loops)
#define N_GRAPHS  64
#define HID       128
#define HEADS     4
#define CH        32
#define N_CLASSES 10
#define N_LAYERS  3
#define NEG_SLOPE 0.2f

// ---------------- scratch (module-load allocated, allowed) ----------------
__device__ __align__(16) float g_xl[N_NODES * HID];
__device__ __align__(16) float g_xr[N_NODES * HID];
__device__ __align__(16) float g_h [N_NODES * HID];
__device__ int   g_deg   [N_NODES];
__device__ int   g_incl  [N_NODES];
__device__ int   g_rowptr[N_NODES + 1];
__device__ int   g_cursor[N_NODES];
__device__ int   g_srcs  [E_TOT];
__device__ int   g_bsums[64];
__device__ int   g_boffs[64];
__device__ int   g_is64;
__device__ __align__(16) float g_pool[N_GRAPHS * HID];
__device__ float g_cnt [N_GRAPHS];

// dtype-robust index load (edge_index / batch may be int32 or int64)
__device__ __forceinline__ int load_idx(const void* p, long i, int is64) {
    if (is64) return (int)((const long long*)p)[i];
    return ((const int*)p)[i];
}

// ---------------- dtype detection -----------------------------------------
__global__ void k_detect(const void* __restrict__ ei) {
    if (threadIdx.x == 0 && blockIdx.x == 0) {
        const long long* p = (const long long*)ei;
        int ok = 1;
        for (int i = 0; i < 256; i++) {
            long long v = p[i];
            if (v < 0 || v >= N_NODES) { ok = 0; break; }
        }
        g_is64 = ok;
    }
}

// ---------------- CSR build (dst is layer-invariant; built once/launch) ---
__global__ void k_zero_deg() {
    int i = blockIdx.x * blockDim.x + threadIdx.x;
    if (i < N_NODES) g_deg[i] = 0;
}

__global__ void k_count(const void* __restrict__ ei) {
    int i = blockIdx.x * blockDim.x + threadIdx.x;
    int is64 = g_is64;
    if (i < E_TOT) {
        int dst = (i < N_EDGES) ? load_idx(ei, (long)N_EDGES + i, is64)
                                : (i - N_EDGES);
        if (dst >= 0 && dst < N_NODES) atomicAdd(&g_deg[dst], 1);
    }
}

__global__ void k_scan_block() {   // 49 blocks x 1024, Hillis-Steele
    __shared__ int s[1024];
    int i = blockIdx.x * 1024 + threadIdx.x;
    int v = (i < N_NODES) ? g_deg[i] : 0;
    s[threadIdx.x] = v;
    __syncthreads();
    for (int off = 1; off < 1024; off <<= 1) {
        int t = 0;
        if (threadIdx.x >= off) t = s[threadIdx.x - off];
        __syncthreads();
        if (threadIdx.x >= off) s[threadIdx.x] += t;
        __syncthreads();
    }
    if (i < N_NODES) g_incl[i] = s[threadIdx.x];
    if (threadIdx.x == 1023) g_bsums[blockIdx.x] = s[1023];
}

__global__ void k_scan_sums(int nb) {
    if (blockIdx.x == 0 && threadIdx.x == 0) {
        int acc = 0;
        for (int b = 0; b < nb; b++) { g_boffs[b] = acc; acc += g_bsums[b]; }
    }
}

__global__ void k_scan_final() {
    int i = blockIdx.x * blockDim.x + threadIdx.x;
    if (i < N_NODES) {
        int rp = g_incl[i] - g_deg[i] + g_boffs[i >> 10];
        g_rowptr[i] = rp;
        g_cursor[i] = rp;
    }
    if (i == 0) g_rowptr[N_NODES] = E_TOT;
}

__global__ void k_scatter(const void* __restrict__ ei) {
    int i = blockIdx.x * blockDim.x + threadIdx.x;
    int is64 = g_is64;
    if (i < E_TOT) {
        int src, dst;
        if (i < N_EDGES) {
            src = load_idx(ei, i, is64);
            dst = load_idx(ei, (long)N_EDGES + i, is64);
        } else {
            src = dst = i - N_EDGES;
        }
        if (src >= 0 && src < N_NODES && dst >= 0 && dst < N_NODES) {
            int pos = atomicAdd(&g_cursor[dst], 1);
            g_srcs[pos] = src;
        }
    }
}

// ---------------- GEMM: out[64rows x 128] = hin @ W + b -------------------
// use_x != 0 -> input is x_in (layer 0), else g_h.
// out_sel: 0 -> g_xl, 1 -> g_xr.
__global__ __launch_bounds__(256)
void k_gemm(const float* __restrict__ x_in, int use_x,
            const float* __restrict__ W,
            const float* __restrict__ b, int out_sel) {
    const float* __restrict__ hin = use_x ? x_in : g_h;
    float* __restrict__ out = out_sel ? g_xr : g_xl;

    __shared__ float As[16][65];
    __shared__ __align__(16) float Ws[16][128];
    int row0 = blockIdx.x * 64;
    int tid = threadIdx.x;
    int tx = tid & 31, ty = tid >> 5;   // tx: 4-col group, ty: 8-row group

    float acc[8][4];
#pragma unroll
    for (int r = 0; r < 8; r++)
#pragma unroll
        for (int c = 0; c < 4; c++) acc[r][c] = 0.f;

    for (int kc = 0; kc < 128; kc += 16) {
#pragma unroll
        for (int i = 0; i < 4; i++) {
            int idx = tid + i * 256;
            int kk = idx & 15, r = idx >> 4;
            int row = row0 + r;
            As[kk][r] = (row < N_NODES) ? hin[row * 128 + kc + kk] : 0.f;
        }
#pragma unroll
        for (int i = 0; i < 8; i++) {
            int idx = tid + i * 256;
            int kk = idx >> 7, nn = idx & 127;
            Ws[kk][nn] = W[(kc + kk) * 128 + nn];
        }
        __syncthreads();
#pragma unroll
        for (int k = 0; k < 16; k++) {
            float4 w = *(const float4*)&Ws[k][tx * 4];
#pragma unroll
            for (int r = 0; r < 8; r++) {
                float a = As[k][ty * 8 + r];   // broadcast within warp
                acc[r][0] += a * w.x; acc[r][1] += a * w.y;
                acc[r][2] += a * w.z; acc[r][3] += a * w.w;
            }
        }
        __syncthreads();
    }
    float4 bb = *(const float4*)&b[tx * 4];
#pragma unroll
    for (int r = 0; r < 8; r++) {
        int row = row0 + ty * 8 + r;
        if (row < N_NODES) {
            float4 o;
            o.x = acc[r][0] + bb.x; o.y = acc[r][1] + bb.y;
            o.z = acc[r][2] + bb.z; o.w = acc[r][3] + bb.w;
            *(float4*)&out[row * 128 + tx * 4] = o;
        }
    }
}

// ------- fused GATv2 edge phase: one warp per destination node ------------
// lane -> (head h = lane>>3, channels (lane&7)*4 .. +3)
// Edge score is recomputed in pass 2 from the xl row (which pass 2 must load
// anyway) -> no global e buffer, no store/load hazard, less L2 traffic.
__global__ __launch_bounds__(256)
void k_attn(const float* __restrict__ att_l, const float* __restrict__ bias_l) {
    int warp = (blockIdx.x * blockDim.x + threadIdx.x) >> 5;
    if (warp >= N_NODES) return;
    int lane = threadIdx.x & 31;
    int d = warp;
    int off = (lane >> 3) * 32 + (lane & 7) * 4;

    float4 xr4 = *(const float4*)&g_xr[d * 128 + off];
    float4 a4  = *(const float4*)&att_l[off];
    int beg = g_rowptr[d], end = g_rowptr[d + 1];

    // pass 1: per-head running max of edge scores
    float m = -1e30f;
    for (int j = beg; j < end; j++) {
        int s = g_srcs[j];
        float4 xs = *(const float4*)&g_xl[s * 128 + off];
        float t0 = xs.x + xr4.x; t0 = t0 > 0.f ? t0 : NEG_SLOPE * t0;
        float t1 = xs.y + xr4.y; t1 = t1 > 0.f ? t1 : NEG_SLOPE * t1;
        float t2 = xs.z + xr4.z; t2 = t2 > 0.f ? t2 : NEG_SLOPE * t2;
        float t3 = xs.w + xr4.w; t3 = t3 > 0.f ? t3 : NEG_SLOPE * t3;
        float p = a4.x * t0 + a4.y * t1 + a4.z * t2 + a4.w * t3;
        p += __shfl_xor_sync(0xffffffffu, p, 1);
        p += __shfl_xor_sync(0xffffffffu, p, 2);
        p += __shfl_xor_sync(0xffffffffu, p, 4);   // all 8 lanes of head hold e
        m = fmaxf(m, p);
    }

    // pass 2: recompute score, exp, denominator, weighted aggregate
    float denom = 0.f;
    float ax = 0.f, ay = 0.f, az = 0.f, aw = 0.f;
    for (int j = beg; j < end; j++) {
        int s = g_srcs[j];
        float4 xs = *(const float4*)&g_xl[s * 128 + off];
        float t0 = xs.x + xr4.x; t0 = t0 > 0.f ? t0 : NEG_SLOPE * t0;
        float t1 = xs.y + xr4.y; t1 = t1 > 0.f ? t1 : NEG_SLOPE * t1;
        float t2 = xs.z + xr4.z; t2 = t2 > 0.f ? t2 : NEG_SLOPE * t2;
        float t3 = xs.w + xr4.w; t3 = t3 > 0.f ? t3 : NEG_SLOPE * t3;
        float p = a4.x * t0 + a4.y * t1 + a4.z * t2 + a4.w * t3;
        p += __shfl_xor_sync(0xffffffffu, p, 1);
        p += __shfl_xor_sync(0xffffffffu, p, 2);
        p += __shfl_xor_sync(0xffffffffu, p, 4);
        float ee = __expf(p - m);
        denom += ee;
        ax += ee * xs.x; ay += ee * xs.y; az += ee * xs.z; aw += ee * xs.w;
    }
    float inv = 1.f / denom;
    float4 bb = *(const float4*)&bias_l[off];
    float o0 = ax * inv + bb.x; o0 = o0 > 0.f ? o0 : expm1f(o0);
    float o1 = ay * inv + bb.y; o1 = o1 > 0.f ? o1 : expm1f(o1);
    float o2 = az * inv + bb.z; o2 = o2 > 0.f ? o2 : expm1f(o2);
    float o3 = aw * inv + bb.w; o3 = o3 > 0.f ? o3 : expm1f(o3);
    float4 o; o.x = o0; o.y = o1; o.z = o2; o.w = o3;
    *(float4*)&g_h[d * 128 + off] = o;
}

// ---------------- pooling + classifier head -------------------------------
__global__ void k_zero_pool() {
    int i = blockIdx.x * blockDim.x + threadIdx.x;
    if (i < N_GRAPHS * HID) g_pool[i] = 0.f;
    if (i < N_GRAPHS) g_cnt[i] = 0.f;
}

__global__ void k_pool(const void* __restrict__ batch) {
    int idx = blockIdx.x * blockDim.x + threadIdx.x;
    int is64 = g_is64;
    if (idx < N_NODES * HID) {
        int n = idx >> 7, c = idx & 127;
        int b = load_idx(batch, n, is64);
        if (b >= 0 && b < N_GRAPHS) {
            atomicAdd(&g_pool[b * 128 + c], g_h[idx]);
            if (c == 0) atomicAdd(&g_cnt[b], 1.f);
        }
    }
}

__global__ void k_final(const float* __restrict__ lin_w,
                        const float* __restrict__ lin_b,
                        float* __restrict__ out) {
    int g = blockIdx.x;
    int lane = threadIdx.x;          // 32 threads/block
    float z = -1e30f, zv = 0.f;
    if (lane < N_CLASSES) {
        float invc = 1.f / fmaxf(g_cnt[g], 1.f);
        float acc = lin_b[lane];
        for (int k = 0; k < 128; k++)
            acc += g_pool[g * 128 + k] * invc * lin_w[k * N_CLASSES + lane];
        acc = acc > 0.f ? acc : expm1f(acc);   // elu
        zv = acc; z = acc;
    }
    float zm = z;
    for (int o = 16; o; o >>= 1) zm = fmaxf(zm, __shfl_xor_sync(0xffffffffu, zm, o));
    float ez = (lane < N_CLASSES) ? __expf(zv - zm) : 0.f;
    float se = ez;
    for (int o = 16; o; o >>= 1) se += __shfl_xor_sync(0xffffffffu, se, o);
    if (lane < N_CLASSES) out[g * N_CLASSES + lane] = zv - zm - logf(se);
}

// ---------------- launcher: kernel launches ONLY --------------------------
extern "C" void kernel_launch(void* const* d_in, const int* in_sizes, int n_in,
                              void* d_out, int out_size) {
    (void)in_sizes; (void)n_in; (void)out_size;
    const float* x     = (const float*)d_in[0];
    const void*  ei    = d_in[1];
    const void*  batch = d_in[2];
    const float* Wl    = (const float*)d_in[3];
    const float* Wr    = (const float*)d_in[4];
    const float* bl    = (const float*)d_in[5];
    const float* br    = (const float*)d_in[6];
    const float* att   = (const float*)d_in[7];
    const float* bias  = (const float*)d_in[8];
    const float* lin_w = (const float*)d_in[9];
    const float* lin_b = (const float*)d_in[10];
    float* out = (float*)d_out;

    // index dtype detection + CSR by destination (layer-invariant)
    k_detect    <<<1, 32>>>(ei);
    k_zero_deg  <<<(N_NODES + 255) / 256, 256>>>();
    k_count     <<<(E_TOT   + 255) / 256, 256>>>(ei);
    int nb = (N_NODES + 1023) / 1024;
    k_scan_block<<<nb, 1024>>>();
    k_scan_sums <<<1, 1>>>(nb);
    k_scan_final<<<(N_NODES + 255) / 256, 256>>>();
    k_scatter   <<<(E_TOT   + 255) / 256, 256>>>(ei);

    const int gemm_grid = (N_NODES + 63) / 64;
    const int attn_grid = (N_NODES * 32 + 255) / 256;
    for (int l = 0; l < N_LAYERS; l++) {
        int use_x = (l == 0) ? 1 : 0;
        k_gemm<<<gemm_grid, 256>>>(x, use_x, Wl + l * 128 * 128, bl + l * 128, 0);
        k_gemm<<<gemm_grid, 256>>>(x, use_x, Wr + l * 128 * 128, br + l * 128, 1);
        k_attn<<<attn_grid, 256>>>(att + l * 128, bias + l * 128);
    }

    k_zero_pool<<<(N_GRAPHS * HID + 255) / 256, 256>>>();
    k_pool     <<<(N_NODES * HID + 255) / 256, 256>>>(batch);
    k_final    <<<N_GRAPHS, 32>>>(lin_w, lin_b, out);
}